// round 13
// baseline (speedup 1.0000x reference)
#include <cuda_runtime.h>

// Gammatone filterbank: 4 cascaded complex one-pole IIRs.
// B=8, T=32000, C=128. Output [B, T, C] fp32.
//
// Round 10: FFMA2 is half-rate (rt=4/SMSP) -> one warp saturates an SMSP's
// fp32 pipe. Launch exactly 592 warps (148 blocks x 4), give each warp ONE
// long chunk-pair (both f32x2 lanes = two time chunks of one channel),
// with per-channel-group chunk lengths balanced against their warm-up halo:
//   group g (channels 32g..32g+31): N_g pairs of length L_g, H_g + L_g ~ const.
// Halo work drops from 45% to ~29% of total. Zero-padded staging makes the
// t<0 boundary exact (zero initial state), single uniform code path.

#define TT 32000
#define CC 128
#define BB 8
#define NTHR 128
#define NBLK 148
#define WPB  74            // warps per batch
#define WBUF 1280          // per-warp staging entries (float2)

typedef unsigned long long u64;

__device__ __forceinline__ u64 pack2(float lo, float hi) {
    u64 r; asm("mov.b64 %0, {%1, %2};" : "=l"(r) : "f"(lo), "f"(hi)); return r;
}
__device__ __forceinline__ void unpack2(float& lo, float& hi, u64 v) {
    asm("mov.b64 {%0, %1}, %2;" : "=f"(lo), "=f"(hi) : "l"(v));
}
__device__ __forceinline__ u64 fma2(u64 a, u64 b, u64 c) {
    u64 d; asm("fma.rn.f32x2 %0, %1, %2, %3;" : "=l"(d) : "l"(a), "l"(b), "l"(c)); return d;
}
__device__ __forceinline__ u64 mul2(u64 a, u64 b) {
    u64 d; asm("mul.rn.f32x2 %0, %1, %2;" : "=l"(d) : "l"(a), "l"(b)); return d;
}

// Delayed-update step (all 4 stages read previous-step values -> 4 independent
// 2-deep FMA chains; equals true cascade delayed by 3 samples, exact).
#define DSTEP(x) do {                                          \
    u64 n4r = fma2(cr2, s4r, s3r); n4r = fma2(cin2, s4i, n4r); \
    u64 n4i = fma2(cr2, s4i, s3i); n4i = fma2(ci2,  s4r, n4i); \
    u64 n3r = fma2(cr2, s3r, s2r); n3r = fma2(cin2, s3i, n3r); \
    u64 n3i = fma2(cr2, s3i, s2i); n3i = fma2(ci2,  s3r, n3i); \
    u64 n2r = fma2(cr2, s2r, s1r); n2r = fma2(cin2, s2i, n2r); \
    u64 n2i = fma2(cr2, s2i, s1i); n2i = fma2(ci2,  s2r, n2i); \
    u64 n1r = fma2(cr2, s1r, (x)); n1r = fma2(cin2, s1i, n1r); \
    u64 n1i = mul2(cr2, s1i);      n1i = fma2(ci2,  s1r, n1i); \
    s4r = n4r; s4i = n4i; s3r = n3r; s3i = n3i;                \
    s2r = n2r; s2i = n2i; s1r = n1r; s1i = n1i; } while (0)

__global__ __launch_bounds__(NTHR)
void gammatone_kernel(const float* __restrict__ inp,
                      const float* __restrict__ coef_re,
                      const float* __restrict__ coef_im,
                      const float* __restrict__ factor,
                      float* __restrict__ out)
{
    __shared__ float2 xs[4][WBUF];   // one private window per warp (40 KB)

    const int tid  = threadIdx.x;
    const int widx = tid >> 5;
    const int lane = tid & 31;

    const int w = blockIdx.x * 4 + widx;   // 0..591
    const int b = w / WPB;                 // batch
    const int r = w % WPB;

    // Per-group chunk schedule: N = {27,18,15,14} pairs, L balanced vs halo.
    int g, k, L;
    if      (r < 27) { g = 0; k = r;      L = 593;  }
    else if (r < 45) { g = 1; k = r - 27; L = 889;  }
    else if (r < 60) { g = 2; k = r - 45; L = 1067; }
    else             { g = 3; k = r - 60; L = 1143; }
    const int hcap = WBUF - L - 4;
    const int c  = g * 32 + lane;          // channel
    const int tA = k * 2 * L;              // lane0 chunk start; lane1 = tA + L

    const float cr = coef_re[c];
    const float ci = coef_im[c];
    const float f  = factor[c];
    const u64 cr2  = pack2(cr,  cr);
    const u64 ci2  = pack2(ci,  ci);
    const u64 cin2 = pack2(-ci, -ci);
    const u64 f2   = pack2(f,   f);

    // Per-warp adaptive warm-up length (warp = one 32-channel group).
    float rr = fminf(sqrtf(cr * cr + ci * ci), 0.9999f);
    int H = (int)ceilf(10.0f / (-__logf(rr))) + 48;
    H = min(H, hcap);
    H = (int)__reduce_max_sync(0xffffffffu, (unsigned)H);

    // Stage zero-padded input window (zero-pad = exact zero initial state).
    // Entry i: lane0 = x[tA-H+i], lane1 = x[tA+L-H+i].
    const float* ib = inp + b * TT;
    const int total = H + L + 3;
    const int base0 = tA - H;
    const int base1 = tA + L - H;
    float2* xw = xs[widx];
    for (int i = lane; i < total; i += 32) {
        int j0 = base0 + i;
        int j1 = base1 + i;
        float v0 = (j0 >= 0 && j0 < TT) ? ib[j0] : 0.0f;
        float v1 = (j1 >= 0 && j1 < TT) ? ib[j1] : 0.0f;
        xw[i] = make_float2(v0, v1);
    }
    __syncwarp();

    u64 s1r = 0, s1i = 0, s2r = 0, s2i = 0;
    u64 s3r = 0, s3i = 0, s4r = 0, s4i = 0;

    const u64* xb = (const u64*)xw;

    // Warm-up: H + 3 steps (3 extra prime the delayed pipeline).
    const int nwu = H + 3;
    #pragma unroll 4
    for (int i = 0; i < nwu; ++i)
        DSTEP(xb[i]);

    // Emit: step i consumes entry H+3+i; s4 = y[tA+i] (lane0) / y[tA+L+i] (lane1).
    const u64* xe = xb + nwu;
    float* oA = out + ((size_t)(b * TT + tA)) * CC + c;
    float* oB = oA + (size_t)L * CC;
    const int nB = min(L, TT - (tA + L));   // lane1 valid rows (tail clamp)
    #pragma unroll 4
    for (int i = 0; i < L; ++i) {
        DSTEP(xe[i]);
        float lo, hi;
        unpack2(lo, hi, mul2(s4r, f2));
        oA[(size_t)i * CC] = lo;
        if (i < nB)
            oB[(size_t)i * CC] = hi;
    }
}

extern "C" void kernel_launch(void* const* d_in, const int* in_sizes, int n_in,
                              void* d_out, int out_size)
{
    const float* inp     = (const float*)d_in[0];
    const float* coef_re = (const float*)d_in[1];
    const float* coef_im = (const float*)d_in[2];
    const float* factor  = (const float*)d_in[3];
    float* out = (float*)d_out;

    gammatone_kernel<<<NBLK, NTHR>>>(inp, coef_re, coef_im, factor, out);
}